// round 9
// baseline (speedup 1.0000x reference)
#include <cuda_runtime.h>
#include <cuda_bf16.h>
#include <cstdint>
#include <math.h>

#define T_STEPS 2048
#define BATCH   64
#define EDIM    256
#define HDIM    256
#define G4      1024
#define VOCAB   50257
#define TBsz    (T_STEPS*BATCH)

typedef unsigned long long ull;

// ---------------- device scratch (no cudaMalloc allowed) ----------------
__device__ float d_P[(size_t)VOCAB * G4];   // projected embedding table, permuted cols

// permutation: j = g*256 + k, k = r*32+u  ->  pj = r*128 + g*32 + u
__device__ __forceinline__ int permj(int j) {
    int g = j >> 8; int k = j & 255; int r = k >> 5; int u = k & 31;
    return r * 128 + g * 32 + u;
}

__device__ __forceinline__ ull pack2(float a, float b) {
    ull r; asm("mov.b64 %0, {%1, %2};" : "=l"(r) : "f"(a), "f"(b)); return r;
}
__device__ __forceinline__ void fma2(ull& d, ull a, ull b) {
    asm("fma.rn.f32x2 %0, %1, %2, %0;" : "+l"(d) : "l"(a), "l"(b));
}
union F2 { ull u; float2 f; };

// ---------------- kernel 1: P = emb @ W_ih^T (NT gemm), permuted cols, f32x2 ----------------
#define BM 128
#define BN 128
#define BK 32
__global__ void __launch_bounds__(256)
proj_kernel(const float* __restrict__ emb, const float* __restrict__ Wih) {
    __shared__ float As[BK][BM + 1];
    __shared__ float Bs[BK][BN + 1];
    int l  = threadIdx.x;
    int v0 = blockIdx.x * BM;
    int j0 = blockIdx.y * BN;
    int ty = l >> 4, tx = l & 15;

    ull acc2[8][4];
#pragma unroll
    for (int i = 0; i < 8; i++)
#pragma unroll
        for (int j = 0; j < 4; j++) acc2[i][j] = 0ull;

    for (int kt = 0; kt < EDIM; kt += BK) {
        for (int idx = l; idx < BM * BK; idx += 256) {
            int vr = idx >> 5; int e = idx & 31;
            int v = v0 + vr;
            As[e][vr] = (v < VOCAB) ? emb[v * EDIM + kt + e] : 0.f;
        }
        for (int idx = l; idx < BN * BK; idx += 256) {
            int jr = idx >> 5; int e = idx & 31;
            Bs[e][jr] = Wih[(j0 + jr) * EDIM + kt + e];
        }
        __syncthreads();
#pragma unroll
        for (int kk = 0; kk < BK; kk++) {
            float a[8], b[8];
#pragma unroll
            for (int i = 0; i < 8; i++) a[i] = As[kk][ty * 8 + i];
#pragma unroll
            for (int i = 0; i < 8; i++) b[i] = Bs[kk][tx * 8 + i];
            ull pa[8], pb[4];
#pragma unroll
            for (int i = 0; i < 8; i++) pa[i] = pack2(a[i], a[i]);
#pragma unroll
            for (int j = 0; j < 4; j++) pb[j] = pack2(b[2 * j], b[2 * j + 1]);
#pragma unroll
            for (int i = 0; i < 8; i++)
#pragma unroll
                for (int j = 0; j < 4; j++) fma2(acc2[i][j], pa[i], pb[j]);
        }
        __syncthreads();
    }
    int jb  = j0 + tx * 8;
    int pj0 = permj(jb);
#pragma unroll
    for (int i = 0; i < 8; i++) {
        int v = v0 + ty * 8 + i;
        if (v < VOCAB) {
#pragma unroll
            for (int j = 0; j < 4; j++) {
                F2 x; x.u = acc2[i][j];
                d_P[(size_t)v * G4 + pj0 + 2 * j]     = x.f.x;
                d_P[(size_t)v * G4 + pj0 + 2 * j + 1] = x.f.y;
            }
        }
    }
}

// ---------------- kernel 2: persistent cluster LSTM, column-pipelined ----------------
__device__ __forceinline__ void cluster_sync_() {
    asm volatile("barrier.cluster.arrive.aligned;" ::: "memory");
    asm volatile("barrier.cluster.wait.aligned;" ::: "memory");
}
__device__ __forceinline__ float sigf(float x) {
    return __fdividef(1.f, 1.f + __expf(-x));
}
__device__ __forceinline__ float tanhfast(float x) {
    return 1.f - 2.f * __fdividef(1.f, __expf(2.f * x) + 1.f);
}
__device__ __forceinline__ void mbar_wait_parity(uint32_t addr, uint32_t ph) {
    uint32_t done;
    asm volatile("{\n\t.reg .pred p;\n\t"
                 "mbarrier.try_wait.parity.acquire.cta.shared::cta.b64 p, [%1], %2;\n\t"
                 "selp.b32 %0, 1, 0, p;\n\t}"
                 : "=r"(done) : "r"(addr), "r"(ph) : "memory");
    if (!done) {
        asm volatile("{\n\t.reg .pred P1;\n\t"
                     "WL_%=:\n\t"
                     "mbarrier.try_wait.parity.acquire.cta.shared::cta.b64 P1, [%0], %1, 0x989680;\n\t"
                     "@P1 bra.uni WD_%=;\n\t"
                     "bra.uni WL_%=;\n\t"
                     "WD_%=:\n\t}"
                     :: "r"(addr), "r"(ph) : "memory");
    }
}

// smem float layout
#define SM_MB    0        // 16 floats = 8 x u64 mbarriers (4 cols x 2 parities)
#define SM_HB    16       // 2048 : 2 par x 4 col x 256 k
#define SM_PART  2064     // 1024 : 4 col-bufs x (2 kh x 128 row)
#define SM_WZ    3088     // 256
#define SM_ZB    3344     // 64 ints of z bits
#define SM_FLOATS 3408
#define LSTM_SMEM_BYTES (SM_FLOATS * 4)

__global__ void __launch_bounds__(256, 1) __cluster_dims__(8, 1, 1)
lstm_kernel(const int* __restrict__ sentences, const float* __restrict__ noise,
            const float* __restrict__ W_hh, const float* __restrict__ b_ih,
            const float* __restrict__ b_hh,
            const float* __restrict__ W_z, const float* __restrict__ b_z_p,
            float* __restrict__ out) {
    extern __shared__ float sm[];
    float* sm_hbuf  = sm + SM_HB;
    float* sm_part  = sm + SM_PART;
    float* sm_Wz    = sm + SM_WZ;
    int*   sm_zbits = (int*)(sm + SM_ZB);

    int tid = threadIdx.x;
    uint32_t r;
    asm("mov.u32 %0, %%cluster_ctarank;" : "=r"(r));
    int cid   = blockIdx.x >> 3;
    int colg0 = cid * 4;
    int row = tid & 127;          // gate-row within CTA slice (g*32+uu)
    int kh  = tid >> 7;           // K-half
    int u   = tid & 31;
    int wrp = tid >> 5;
    bool is_owner = (wrp < 4);    // warp c owns column c's pointwise+ship

    // register-resident weights (same mapping as before):
    // slice row (g*32+uu) of CTA r  <->  original row j = g*256 + r*32 + uu
    ull wp[64];
    {
        int g = row >> 5, uu = row & 31;
        int j = g * 256 + (int)r * 32 + uu;
        const float2* wsrc = (const float2*)(W_hh + j * 256 + kh * 128);
#pragma unroll
        for (int i = 0; i < 64; i++) {
            float2 w = wsrc[i];
            wp[i] = pack2(w.x, w.y);
        }
    }

    sm_Wz[tid] = W_z[tid & 255];
    for (int idx = tid; idx < 2048; idx += 256) sm_hbuf[idx] = 0.f;
    for (int idx = tid; idx < 64; idx += 256) sm_zbits[idx] = 0;

    // 8 mbarriers: [c][parity]; init count=1 and pre-arm 1024B (8 peers x 32 x 4B)
    uint32_t mb_local = (uint32_t)__cvta_generic_to_shared(sm + SM_MB);
    if (tid == 0) {
#pragma unroll
        for (int b8 = 0; b8 < 8; b8++) {
            asm volatile("mbarrier.init.shared.b64 [%0], 1;" :: "r"(mb_local + b8 * 8) : "memory");
            asm volatile("mbarrier.arrive.expect_tx.shared.b64 _, [%0], 1024;" :: "r"(mb_local + b8 * 8) : "memory");
        }
    }

    // owner constants
    float b0 = 0.f, b1 = 0.f, b2 = 0.f, b3 = 0.f, creg = 0.f;
    if (is_owner) {
        int jb0 = (int)r * 32 + u;
        b0 = b_ih[jb0]       + b_hh[jb0];
        b1 = b_ih[jb0 + 256] + b_hh[jb0 + 256];
        b2 = b_ih[jb0 + 512] + b_hh[jb0 + 512];
        b3 = b_ih[jb0 + 768] + b_hh[jb0 + 768];
    }
    float bz = b_z_p[0];
    __syncthreads();

    // peer addresses
    uint32_t hb_local = (uint32_t)__cvta_generic_to_shared(sm_hbuf);
    uint32_t peer_hb[8], peer_mb[8];
#pragma unroll
    for (int p = 0; p < 8; p++) {
        asm("mapa.shared::cluster.u32 %0, %1, %2;" : "=r"(peer_hb[p]) : "r"(hb_local), "r"(p));
        asm("mapa.shared::cluster.u32 %0, %1, %2;" : "=r"(peer_mb[p]) : "r"(mb_local), "r"(p));
    }

    // prefetch x-gates for t=0 (owner warp c -> column colg0+c)
    float xg0 = 0.f, xg1 = 0.f, xg2 = 0.f, xg3 = 0.f;
    if (is_owner) {
        int tok = sentences[colg0 + wrp];
        const float* Pp = d_P + (size_t)tok * G4 + (int)r * 128 + u;
        xg0 = Pp[0]; xg1 = Pp[32]; xg2 = Pp[64]; xg3 = Pp[96];
    }

    float nz = 0.f;
    uint32_t zchunk = 0;
    cluster_sync_();                 // all mbarriers initialized cluster-wide

    for (int t = 0; t < T_STEPS; t++) {
        int par  = t & 1;
        int wpar = par ^ 1;

        for (int c = 0; c < 4; c++) {
            // ---- wait for this column's h (skip at t=0: zero-init) ----
            if (t != 0) {
                uint32_t mba = mb_local + (uint32_t)((c * 2 + par) * 8);
                uint32_t ph  = (uint32_t)(((t - 2 + par) >> 1) & 1);
                mbar_wait_parity(mba, ph);
                if (tid == c * 32)
                    asm volatile("mbarrier.arrive.expect_tx.shared.b64 _, [%0], 1024;"
                                 :: "r"(mba) : "memory");
                // pz/z for output t-1 (CTA r<4, its column): safe here — overwrite of
                // this buffer requires our ship(c,t) which is after warp7's arrive(c,t).
                if (wrp == 7 && (int)r < 4 && c == (int)r) {
                    float acc = 0.f;
                    const float* hrow = sm_hbuf + par * 1024 + (int)r * 256;
#pragma unroll
                    for (int jj = 0; jj < 8; jj++)
                        acc += hrow[u + jj * 32] * sm_Wz[u + jj * 32];
#pragma unroll
                    for (int off = 16; off; off >>= 1)
                        acc += __shfl_down_sync(0xffffffffu, acc, off);
                    if (u == 0) {
                        float pz = sigf(acc + bz);
                        int oi = t - 1;
                        int o = oi * BATCH + colg0 + (int)r;
                        uint32_t zb = (nz < pz) ? 1u : 0u;
                        out[o]        = pz;
                        out[TBsz + o] = (float)zb;
                        zchunk |= zb << (oi & 31);
                        if ((oi & 31) == 31) { sm_zbits[oi >> 5] = (int)zchunk; zchunk = 0; }
                        nz = noise[t * BATCH + colg0 + (int)r];
                    }
                }
            } else if (wrp == 7 && (int)r < 4 && c == (int)r && u == 0) {
                nz = noise[colg0 + (int)r];   // noise for output t=0
            }

            // ---- matmul for column c: weights in regs, h via broadcast LDS ----
            ull aA = 0ull, aB = 0ull, aC = 0ull, aD = 0ull;
            {
                const ulonglong2* hp = (const ulonglong2*)(sm_hbuf + par * 1024 + c * 256 + kh * 128);
#pragma unroll
                for (int i = 0; i < 32; i += 2) {
                    ulonglong2 h0 = hp[i];
                    ulonglong2 h1 = hp[i + 1];
                    fma2(aA, wp[2 * i],     h0.x);
                    fma2(aB, wp[2 * i + 1], h0.y);
                    fma2(aC, wp[2 * i + 2], h1.x);
                    fma2(aD, wp[2 * i + 3], h1.y);
                }
            }
            {
                F2 xa, xb, xc, xd;
                xa.u = aA; xb.u = aB; xc.u = aC; xd.u = aD;
                float s = ((xa.f.x + xa.f.y) + (xb.f.x + xb.f.y))
                        + ((xc.f.x + xc.f.y) + (xd.f.x + xd.f.y));
                sm_part[c * 256 + kh * 128 + row] = s;
            }

            // ---- producer/consumer named barrier: only owner blocks ----
            if (wrp == c) {
                asm volatile("bar.sync %0, 256;" :: "r"(c + 1) : "memory");
                // pointwise for column c (lane u = unit u)
                const float* pp = sm_part + c * 256;
                float gi = pp[u]       + pp[128 + u] + xg0 + b0;
                float gf = pp[32 + u]  + pp[160 + u] + xg1 + b1;
                float gg = pp[64 + u]  + pp[192 + u] + xg2 + b2;
                float go = pp[96 + u]  + pp[224 + u] + xg3 + b3;
                creg = sigf(gf) * creg + sigf(gi) * tanhfast(gg);
                float h = sigf(go) * tanhfast(creg);
                // ship h(u, col c) to all 8 CTAs' hbuf[wpar][c][r*32+u]
                uint32_t off  = (uint32_t)((wpar * 1024 + c * 256 + (int)r * 32 + u) * 4);
                uint32_t moff = (uint32_t)((c * 2 + wpar) * 8);
#pragma unroll
                for (int p8 = 0; p8 < 8; p8++)
                    asm volatile("st.async.shared::cluster.mbarrier::complete_tx::bytes.f32 [%0], %1, [%2];"
                                 :: "r"(peer_hb[p8] + off), "f"(h), "r"(peer_mb[p8] + moff) : "memory");
                // prefetch next step's x-gates (hidden under remaining columns)
                if (t + 1 < T_STEPS) {
                    int tok = sentences[(t + 1) * BATCH + colg0 + c];
                    const float* Pp = d_P + (size_t)tok * G4 + (int)r * 128 + u;
                    xg0 = Pp[0]; xg1 = Pp[32]; xg2 = Pp[64]; xg3 = Pp[96];
                }
            } else {
                asm volatile("bar.arrive %0, 256;" :: "r"(c + 1) : "memory");
            }
        }
    }

    // final: h_2047 lands in parity-0 buffers (shipped at t=2047, wpar=0)
    {
#pragma unroll
        for (int c = 0; c < 4; c++)
            mbar_wait_parity(mb_local + (uint32_t)((c * 2) * 8), 1u);
    }
    if (wrp == 7 && (int)r < 4) {
        float acc = 0.f;
        const float* hrow = sm_hbuf + (int)r * 256;   // parity 0
#pragma unroll
        for (int jj = 0; jj < 8; jj++)
            acc += hrow[u + jj * 32] * sm_Wz[u + jj * 32];
#pragma unroll
        for (int off = 16; off; off >>= 1)
            acc += __shfl_down_sync(0xffffffffu, acc, off);
        if (u == 0) {
            float pz = sigf(acc + bz);
            int o = 2047 * BATCH + colg0 + (int)r;
            uint32_t zb = (nz < pz) ? 1u : 0u;
            out[o]        = pz;
            out[TBsz + o] = (float)zb;
            zchunk |= zb << 31;
            sm_zbits[63] = (int)zchunk;
        }
    }
    cluster_sync_();   // no CTA exits while peers' async stores may still target it
    __syncthreads();

    // ---- fused per-column compaction (CTA r<4 handles column colg0+r) ----
    {
        int b = colg0 + (int)r;
        int lane = tid & 31, w = tid >> 5;
        int* wsum = (int*)sm_part;          // scratch
        int* s_total = wsum + 8;

        uint32_t byte = ((uint32_t)sm_zbits[tid >> 2] >> ((tid & 3) * 8)) & 0xFFu;
        int cnt = __popc(byte);
        int x = cnt;
#pragma unroll
        for (int off = 1; off < 32; off <<= 1) {
            int y = __shfl_up_sync(0xffffffffu, x, off);
            if (lane >= off) x += y;
        }
        if (lane == 31) wsum[w] = x;
        __syncthreads();
        if (tid == 0) {
            int s = 0;
            for (int k = 0; k < 8; k++) { int v = wsum[k]; wsum[k] = s; s += v; }
            *s_total = s;
        }
        __syncthreads();
        if ((int)r < 4) {
            int base = wsum[w] + (x - cnt);
            int t0 = tid * 8;
            int pos = base;
#pragma unroll
            for (int k = 0; k < 8; k++) {
                if ((byte >> k) & 1u) {
                    out[2 * TBsz + pos * BATCH + b] = (float)sentences[(t0 + k) * BATCH + b];
                    pos++;
                }
            }
            int total = *s_total;
            for (int p = total + tid; p < T_STEPS; p += 256)
                out[2 * TBsz + p * BATCH + b] = 0.0f;   // PAD_ID = 0
            if (tid == 0) out[3 * TBsz + b] = (float)total;
        }
    }
}

// ---------------- launch ----------------
extern "C" void kernel_launch(void* const* d_in, const int* in_sizes, int n_in,
                              void* d_out, int out_size) {
    const int*   sentences = (const int*)  d_in[0];
    const float* noise     = (const float*)d_in[1];
    const float* emb       = (const float*)d_in[2];
    const float* W_ih      = (const float*)d_in[3];
    const float* W_hh      = (const float*)d_in[4];
    const float* b_ih      = (const float*)d_in[5];
    const float* b_hh      = (const float*)d_in[6];
    const float* W_z       = (const float*)d_in[7];
    const float* b_z       = (const float*)d_in[8];
    float* out = (float*)d_out;

    cudaFuncSetAttribute(lstm_kernel, cudaFuncAttributeMaxDynamicSharedMemorySize,
                         LSTM_SMEM_BYTES);

    proj_kernel<<<dim3((VOCAB + BM - 1) / BM, G4 / BN), 256>>>(emb, W_ih);
    lstm_kernel<<<128, 256, LSTM_SMEM_BYTES>>>(sentences, noise, W_hh, b_ih, b_hh,
                                               W_z, b_z, out);
}

// round 10
// speedup vs baseline: 1.7873x; 1.7873x over previous
#include <cuda_runtime.h>
#include <cuda_bf16.h>
#include <cstdint>
#include <math.h>

#define T_STEPS 2048
#define BATCH   64
#define EDIM    256
#define HDIM    256
#define G4      1024
#define VOCAB   50257
#define TBsz    (T_STEPS*BATCH)

typedef unsigned long long ull;

// ---------------- device scratch (no cudaMalloc allowed) ----------------
__device__ float d_P[(size_t)VOCAB * G4];   // projected embedding table, permuted cols

// permutation: j = g*256 + k, k = r*32+u  ->  pj = r*128 + g*32 + u
__device__ __forceinline__ int permj(int j) {
    int g = j >> 8; int k = j & 255; int r = k >> 5; int u = k & 31;
    return r * 128 + g * 32 + u;
}

__device__ __forceinline__ ull pack2(float a, float b) {
    ull r; asm("mov.b64 %0, {%1, %2};" : "=l"(r) : "f"(a), "f"(b)); return r;
}
__device__ __forceinline__ void fma2(ull& d, ull a, ull b) {
    asm("fma.rn.f32x2 %0, %1, %2, %0;" : "+l"(d) : "l"(a), "l"(b));
}
union F2 { ull u; float2 f; };

// ---------------- kernel 1: P = emb @ W_ih^T (NT gemm), permuted cols, f32x2 ----------------
#define BM 128
#define BN 128
#define BK 32
__global__ void __launch_bounds__(256)
proj_kernel(const float* __restrict__ emb, const float* __restrict__ Wih) {
    __shared__ float As[BK][BM + 1];
    __shared__ float Bs[BK][BN + 1];
    int l  = threadIdx.x;
    int v0 = blockIdx.x * BM;
    int j0 = blockIdx.y * BN;
    int ty = l >> 4, tx = l & 15;

    ull acc2[8][4];
#pragma unroll
    for (int i = 0; i < 8; i++)
#pragma unroll
        for (int j = 0; j < 4; j++) acc2[i][j] = 0ull;

    for (int kt = 0; kt < EDIM; kt += BK) {
        for (int idx = l; idx < BM * BK; idx += 256) {
            int vr = idx >> 5; int e = idx & 31;
            int v = v0 + vr;
            As[e][vr] = (v < VOCAB) ? emb[v * EDIM + kt + e] : 0.f;
        }
        for (int idx = l; idx < BN * BK; idx += 256) {
            int jr = idx >> 5; int e = idx & 31;
            Bs[e][jr] = Wih[(j0 + jr) * EDIM + kt + e];
        }
        __syncthreads();
#pragma unroll
        for (int kk = 0; kk < BK; kk++) {
            float a[8], b[8];
#pragma unroll
            for (int i = 0; i < 8; i++) a[i] = As[kk][ty * 8 + i];
#pragma unroll
            for (int i = 0; i < 8; i++) b[i] = Bs[kk][tx * 8 + i];
            ull pa[8], pb[4];
#pragma unroll
            for (int i = 0; i < 8; i++) pa[i] = pack2(a[i], a[i]);
#pragma unroll
            for (int j = 0; j < 4; j++) pb[j] = pack2(b[2 * j], b[2 * j + 1]);
#pragma unroll
            for (int i = 0; i < 8; i++)
#pragma unroll
                for (int j = 0; j < 4; j++) fma2(acc2[i][j], pa[i], pb[j]);
        }
        __syncthreads();
    }
    int jb  = j0 + tx * 8;
    int pj0 = permj(jb);
#pragma unroll
    for (int i = 0; i < 8; i++) {
        int v = v0 + ty * 8 + i;
        if (v < VOCAB) {
#pragma unroll
            for (int j = 0; j < 4; j++) {
                F2 x; x.u = acc2[i][j];
                d_P[(size_t)v * G4 + pj0 + 2 * j]     = x.f.x;
                d_P[(size_t)v * G4 + pj0 + 2 * j + 1] = x.f.y;
            }
        }
    }
}

// ---------------- kernel 2: persistent cluster LSTM + fused compaction ----------------
__device__ __forceinline__ void cluster_sync_() {
    asm volatile("barrier.cluster.arrive.aligned;" ::: "memory");
    asm volatile("barrier.cluster.wait.aligned;" ::: "memory");
}
__device__ __forceinline__ float sigf(float x) {
    return __fdividef(1.f, 1.f + __expf(-x));
}
__device__ __forceinline__ float tanhfast(float x) {
    return 1.f - 2.f * __fdividef(1.f, __expf(2.f * x) + 1.f);
}
__device__ __forceinline__ void mbar_wait_parity(uint32_t addr, uint32_t ph) {
    uint32_t done;
    asm volatile("{\n\t.reg .pred p;\n\t"
                 "mbarrier.try_wait.parity.acquire.cta.shared::cta.b64 p, [%1], %2;\n\t"
                 "selp.b32 %0, 1, 0, p;\n\t}"
                 : "=r"(done) : "r"(addr), "r"(ph) : "memory");
    if (!done) {
        asm volatile("{\n\t.reg .pred P1;\n\t"
                     "WL_%=:\n\t"
                     "mbarrier.try_wait.parity.acquire.cta.shared::cta.b64 P1, [%0], %1, 0x989680;\n\t"
                     "@P1 bra.uni WD_%=;\n\t"
                     "bra.uni WL_%=;\n\t"
                     "WD_%=:\n\t}"
                     :: "r"(addr), "r"(ph) : "memory");
    }
}

// smem float layout
#define SM_MB    0        // 4 floats = 2 x u64 mbarriers (16B)
#define SM_HB    4        // 2048 : 2 par x 4 col x 256 k
#define SM_PART  2052     // 1024 : 2 kh x 128 row x 4 col (float4/row); int scratch reuse
#define SM_WZ    3076     // 256
#define SM_TOK   3332     // 8 ints (2 par x 4 col)
#define SM_ZB    3340     // 64 ints of z bits
#define SM_FLOATS 3408
#define LSTM_SMEM_BYTES (SM_FLOATS * 4)

__global__ void __launch_bounds__(256, 1) __cluster_dims__(8, 1, 1)
lstm_kernel(const int* __restrict__ sentences, const float* __restrict__ noise,
            const float* __restrict__ W_hh, const float* __restrict__ b_ih,
            const float* __restrict__ b_hh,
            const float* __restrict__ W_z, const float* __restrict__ b_z_p,
            float* __restrict__ out) {
    extern __shared__ float sm[];
    float* sm_hbuf  = sm + SM_HB;
    float* sm_part  = sm + SM_PART;
    float* sm_Wz    = sm + SM_WZ;
    int*   sm_tok   = (int*)(sm + SM_TOK);
    int*   sm_zbits = (int*)(sm + SM_ZB);

    int tid = threadIdx.x;
    uint32_t r;
    asm("mov.u32 %0, %%cluster_ctarank;" : "=r"(r));
    int cid   = blockIdx.x >> 3;
    int colg0 = cid * 4;
    int row = tid & 127;          // gate-row within CTA slice (g*32+uu)
    int kh  = tid >> 7;           // K-half
    int u   = tid & 31;
    int col = (tid >> 5) & 3;
    int wrp = tid >> 5;

    // register-resident weights, loaded with inverse permutation:
    // slice row (g*32+uu) of CTA r  <->  original row j = g*256 + r*32 + uu
    ull wp[64];
    {
        int g = row >> 5, uu = row & 31;
        int j = g * 256 + (int)r * 32 + uu;
        const float2* wsrc = (const float2*)(W_hh + j * 256 + kh * 128);
#pragma unroll
        for (int i = 0; i < 64; i++) {
            float2 w = wsrc[i];
            wp[i] = pack2(w.x, w.y);
        }
    }

    sm_Wz[tid] = W_z[tid & 255];
    for (int idx = tid; idx < 2048; idx += 256) sm_hbuf[idx] = 0.f;
    for (int idx = tid; idx < 64; idx += 256) sm_zbits[idx] = 0;
    if (tid < 4) sm_tok[tid] = sentences[colg0 + tid];

    // mbarriers: init + pre-arm both parities (4096 tx bytes = 512 x 8B msgs)
    uint32_t mb_local = (uint32_t)__cvta_generic_to_shared(sm + SM_MB);
    if (tid == 0) {
        asm volatile("mbarrier.init.shared.b64 [%0], 1;" :: "r"(mb_local)     : "memory");
        asm volatile("mbarrier.init.shared.b64 [%0], 1;" :: "r"(mb_local + 8) : "memory");
        asm volatile("mbarrier.arrive.expect_tx.shared.b64 _, [%0], 4096;" :: "r"(mb_local)     : "memory");
        asm volatile("mbarrier.arrive.expect_tx.shared.b64 _, [%0], 4096;" :: "r"(mb_local + 8) : "memory");
    }

    // pointwise constants (tid<128 -> unit u, col)
    float b0 = 0.f, b1 = 0.f, b2 = 0.f, b3 = 0.f, creg = 0.f;
    if (tid < 128) {
        int jb0 = (int)r * 32 + u;
        b0 = b_ih[jb0]       + b_hh[jb0];
        b1 = b_ih[jb0 + 256] + b_hh[jb0 + 256];
        b2 = b_ih[jb0 + 512] + b_hh[jb0 + 512];
        b3 = b_ih[jb0 + 768] + b_hh[jb0 + 768];
    }
    float bz = b_z_p[0];
    __syncthreads();

    // per-thread exchange descriptors: thread u ships its PAIR (units u&~1, u&~1|1)
    // as one 8B b64 message to 4 peers: even u -> peers 0..3, odd u -> peers 4..7.
    uint32_t hb_local = (uint32_t)__cvta_generic_to_shared(sm_hbuf);
    uint32_t sA0 = 0, sA1 = 0, sA2 = 0, sA3 = 0;   // dest hbuf addrs (4 peers)
    uint32_t mA0 = 0, mA1 = 0, mA2 = 0, mA3 = 0;   // dest mbar addrs
    if (tid < 128) {
        uint32_t base = (uint32_t)((u & 1) * 4);
        uint32_t doff = (uint32_t)((col * 256 + (int)r * 32 + (u & ~1)) * 4);
        uint32_t a;
        asm("mapa.shared::cluster.u32 %0, %1, %2;" : "=r"(a) : "r"(hb_local), "r"(base + 0));
        sA0 = a + doff;
        asm("mapa.shared::cluster.u32 %0, %1, %2;" : "=r"(a) : "r"(hb_local), "r"(base + 1));
        sA1 = a + doff;
        asm("mapa.shared::cluster.u32 %0, %1, %2;" : "=r"(a) : "r"(hb_local), "r"(base + 2));
        sA2 = a + doff;
        asm("mapa.shared::cluster.u32 %0, %1, %2;" : "=r"(a) : "r"(hb_local), "r"(base + 3));
        sA3 = a + doff;
        asm("mapa.shared::cluster.u32 %0, %1, %2;" : "=r"(a) : "r"(mb_local), "r"(base + 0));
        mA0 = a;
        asm("mapa.shared::cluster.u32 %0, %1, %2;" : "=r"(a) : "r"(mb_local), "r"(base + 1));
        mA1 = a;
        asm("mapa.shared::cluster.u32 %0, %1, %2;" : "=r"(a) : "r"(mb_local), "r"(base + 2));
        mA2 = a;
        asm("mapa.shared::cluster.u32 %0, %1, %2;" : "=r"(a) : "r"(mb_local), "r"(base + 3));
        mA3 = a;
    }

    float nz = 0.f;
    uint32_t ph0 = 0, ph1 = 0;
    uint32_t zchunk = 0;
    cluster_sync_();                 // all mbarriers initialized cluster-wide

    for (int t = 0; t < T_STEPS; t++) {
        int par  = t & 1;
        int wpar = par ^ 1;

        // ---- x-gate loads for this step (pointwise threads), overlap matmul ----
        float xg0 = 0.f, xg1 = 0.f, xg2 = 0.f, xg3 = 0.f;
        if (tid < 128) {
            int tok = sm_tok[par * 4 + col];
            const float* Pp = d_P + (size_t)tok * G4 + (int)r * 128 + u;
            xg0 = Pp[0]; xg1 = Pp[32]; xg2 = Pp[64]; xg3 = Pp[96];
        }

        // ---- next-step token prefetch (warp 7 tail) ----
        int nxt_tok = 0;
        if (tid >= 252) {
            int tn = (t + 1 < T_STEPS) ? t + 1 : T_STEPS - 1;
            nxt_tok = sentences[tn * BATCH + colg0 + (tid - 252)];
        }

        // ---- pz/z for output t-1: CTA r (<4), warp 5 ----
        if ((int)r < 4 && wrp == 5 && t > 0) {
            int lane = tid & 31;
            float acc = 0.f;
            const float* hrow = sm_hbuf + par * 1024 + (int)r * 256;
#pragma unroll
            for (int jj = 0; jj < 8; jj++)
                acc += hrow[lane + jj * 32] * sm_Wz[lane + jj * 32];
#pragma unroll
            for (int off = 16; off; off >>= 1)
                acc += __shfl_down_sync(0xffffffffu, acc, off);
            if (lane == 0) {
                float pz = sigf(acc + bz);
                int oi = t - 1;
                int o = oi * BATCH + colg0 + (int)r;
                uint32_t zb = (nz < pz) ? 1u : 0u;
                out[o]        = pz;
                out[TBsz + o] = (float)zb;
                zchunk |= zb << (oi & 31);
                if ((oi & 31) == 31) { sm_zbits[oi >> 5] = (int)zchunk; zchunk = 0; }
            }
        }
        if ((int)r < 4 && tid == 160) nz = noise[t * BATCH + colg0 + (int)r];

        // ---- recurrent matmul: row x 4 cols over K-half, weights in registers ----
        ull aA0 = 0ull, aB0 = 0ull, aA1 = 0ull, aB1 = 0ull;
        ull aA2 = 0ull, aB2 = 0ull, aA3 = 0ull, aB3 = 0ull;
        {
            const ulonglong2* hp0 = (const ulonglong2*)(sm_hbuf + par * 1024 + 0 * 256 + kh * 128);
            const ulonglong2* hp1 = (const ulonglong2*)(sm_hbuf + par * 1024 + 1 * 256 + kh * 128);
            const ulonglong2* hp2 = (const ulonglong2*)(sm_hbuf + par * 1024 + 2 * 256 + kh * 128);
            const ulonglong2* hp3 = (const ulonglong2*)(sm_hbuf + par * 1024 + 3 * 256 + kh * 128);
#pragma unroll
            for (int i = 0; i < 32; i++) {
                ulonglong2 h0 = hp0[i];
                fma2(aA0, wp[2 * i], h0.x); fma2(aB0, wp[2 * i + 1], h0.y);
                ulonglong2 h1 = hp1[i];
                fma2(aA1, wp[2 * i], h1.x); fma2(aB1, wp[2 * i + 1], h1.y);
                ulonglong2 h2 = hp2[i];
                fma2(aA2, wp[2 * i], h2.x); fma2(aB2, wp[2 * i + 1], h2.y);
                ulonglong2 h3 = hp3[i];
                fma2(aA3, wp[2 * i], h3.x); fma2(aB3, wp[2 * i + 1], h3.y);
            }
        }
        {
            F2 xa, xb;
            float s0, s1, s2, s3;
            xa.u = aA0; xb.u = aB0; s0 = (xa.f.x + xa.f.y) + (xb.f.x + xb.f.y);
            xa.u = aA1; xb.u = aB1; s1 = (xa.f.x + xa.f.y) + (xb.f.x + xb.f.y);
            xa.u = aA2; xb.u = aB2; s2 = (xa.f.x + xa.f.y) + (xb.f.x + xb.f.y);
            xa.u = aA3; xb.u = aB3; s3 = (xa.f.x + xa.f.y) + (xb.f.x + xb.f.y);
            ((float4*)sm_part)[kh * 128 + row] = make_float4(s0, s1, s2, s3);
        }
        __syncthreads();

        // ---- pointwise: compute h, pair-fuse via shfl, ship 4 x b64 st.async ----
        if (tid < 128) {
            const float* p0 = sm_part;
            const float* p1 = sm_part + 512;
            float gi = p0[(u)      * 4 + col] + p1[(u)      * 4 + col] + xg0 + b0;
            float gf = p0[(32 + u) * 4 + col] + p1[(32 + u) * 4 + col] + xg1 + b1;
            float gg = p0[(64 + u) * 4 + col] + p1[(64 + u) * 4 + col] + xg2 + b2;
            float go = p0[(96 + u) * 4 + col] + p1[(96 + u) * 4 + col] + xg3 + b3;
            creg = sigf(gf) * creg + sigf(gi) * tanhfast(gg);
            float h = sigf(go) * tanhfast(creg);
            // pair with partner unit (u^1); both threads build the same 8B payload
            float other = __shfl_xor_sync(0xffffffffu, h, 1);
            ull pay = (u & 1) ? pack2(other, h) : pack2(h, other);
            uint32_t bo = (uint32_t)(wpar * 4096);
            uint32_t mo = (uint32_t)(wpar * 8);
            asm volatile("st.async.shared::cluster.mbarrier::complete_tx::bytes.b64 [%0], %1, [%2];"
                         :: "r"(sA0 + bo), "l"(pay), "r"(mA0 + mo) : "memory");
            asm volatile("st.async.shared::cluster.mbarrier::complete_tx::bytes.b64 [%0], %1, [%2];"
                         :: "r"(sA1 + bo), "l"(pay), "r"(mA1 + mo) : "memory");
            asm volatile("st.async.shared::cluster.mbarrier::complete_tx::bytes.b64 [%0], %1, [%2];"
                         :: "r"(sA2 + bo), "l"(pay), "r"(mA2 + mo) : "memory");
            asm volatile("st.async.shared::cluster.mbarrier::complete_tx::bytes.b64 [%0], %1, [%2];"
                         :: "r"(sA3 + bo), "l"(pay), "r"(mA3 + mo) : "memory");
        }

        // stage next tokens while stores fly
        if (tid >= 252) sm_tok[((t + 1) & 1) * 4 + (tid - 252)] = nxt_tok;

        // ---- wait for all 8 CTAs' h-slices (4096 tx bytes), then re-arm ----
        if (wpar == 0) { mbar_wait_parity(mb_local,     ph0); ph0 ^= 1; }
        else           { mbar_wait_parity(mb_local + 8, ph1); ph1 ^= 1; }
        if (tid == 0)
            asm volatile("mbarrier.arrive.expect_tx.shared.b64 _, [%0], 4096;"
                         :: "r"(mb_local + (uint32_t)(wpar * 8)) : "memory");
    }

    // final pz for t_out = 2047 (h_2047 is in parity 0)
    if ((int)r < 4 && wrp == 5) {
        int lane = tid & 31;
        float acc = 0.f;
        const float* hrow = sm_hbuf + (int)r * 256;
#pragma unroll
        for (int jj = 0; jj < 8; jj++)
            acc += hrow[lane + jj * 32] * sm_Wz[lane + jj * 32];
#pragma unroll
        for (int off = 16; off; off >>= 1)
            acc += __shfl_down_sync(0xffffffffu, acc, off);
        if (lane == 0) {
            float pz = sigf(acc + bz);
            int o = 2047 * BATCH + colg0 + (int)r;
            uint32_t zb = (nz < pz) ? 1u : 0u;
            out[o]        = pz;
            out[TBsz + o] = (float)zb;
            zchunk |= zb << 31;
            sm_zbits[63] = (int)zchunk;
        }
    }
    cluster_sync_();   // no CTA exits while peers' async stores may still target it
    __syncthreads();

    // ---- fused per-column compaction (CTA r<4 handles column colg0+r) ----
    {
        int b = colg0 + (int)r;
        int lane = tid & 31, w = tid >> 5;
        int* wsum = (int*)sm_part;          // scratch
        int* s_total = wsum + 8;

        uint32_t byte = ((uint32_t)sm_zbits[tid >> 2] >> ((tid & 3) * 8)) & 0xFFu;
        int cnt = __popc(byte);
        int x = cnt;
#pragma unroll
        for (int off = 1; off < 32; off <<= 1) {
            int y = __shfl_up_sync(0xffffffffu, x, off);
            if (lane >= off) x += y;
        }
        if (lane == 31) wsum[w] = x;
        __syncthreads();
        if (tid == 0) {
            int s = 0;
            for (int k = 0; k < 8; k++) { int v = wsum[k]; wsum[k] = s; s += v; }
            *s_total = s;
        }
        __syncthreads();
        if ((int)r < 4) {
            int base = wsum[w] + (x - cnt);
            int t0 = tid * 8;
            int pos = base;
#pragma unroll
            for (int k = 0; k < 8; k++) {
                if ((byte >> k) & 1u) {
                    out[2 * TBsz + pos * BATCH + b] = (float)sentences[(t0 + k) * BATCH + b];
                    pos++;
                }
            }
            int total = *s_total;
            for (int p = total + tid; p < T_STEPS; p += 256)
                out[2 * TBsz + p * BATCH + b] = 0.0f;   // PAD_ID = 0
            if (tid == 0) out[3 * TBsz + b] = (float)total;
        }
    }
}

// ---------------- launch ----------------
extern "C" void kernel_launch(void* const* d_in, const int* in_sizes, int n_in,
                              void* d_out, int out_size) {
    const int*   sentences = (const int*)  d_in[0];
    const float* noise     = (const float*)d_in[1];
    const float* emb       = (const float*)d_in[2];
    const float* W_ih      = (const float*)d_in[3];
    const float* W_hh      = (const float*)d_in[4];
    const float* b_ih      = (const float*)d_in[5];
    const float* b_hh      = (const float*)d_in[6];
    const float* W_z       = (const float*)d_in[7];
    const float* b_z       = (const float*)d_in[8];
    float* out = (float*)d_out;

    cudaFuncSetAttribute(lstm_kernel, cudaFuncAttributeMaxDynamicSharedMemorySize,
                         LSTM_SMEM_BYTES);

    proj_kernel<<<dim3((VOCAB + BM - 1) / BM, G4 / BN), 256>>>(emb, W_ih);
    lstm_kernel<<<128, 256, LSTM_SMEM_BYTES>>>(sentences, noise, W_hh, b_ih, b_hh,
                                               W_z, b_z, out);
}

// round 12
// speedup vs baseline: 1.8565x; 1.0387x over previous
#include <cuda_runtime.h>
#include <cuda_bf16.h>
#include <cstdint>
#include <math.h>

#define T_STEPS 2048
#define BATCH   64
#define EDIM    256
#define HDIM    256
#define G4      1024
#define VOCAB   50257
#define TBsz    (T_STEPS*BATCH)

typedef unsigned long long ull;

// ---------------- device scratch (no cudaMalloc allowed) ----------------
__device__ float d_P[(size_t)VOCAB * G4];   // projected embedding table, permuted cols

// permutation: j = g*256 + k, k = r*32+u  ->  pj = r*128 + g*32 + u
__device__ __forceinline__ int permj(int j) {
    int g = j >> 8; int k = j & 255; int r = k >> 5; int u = k & 31;
    return r * 128 + g * 32 + u;
}

__device__ __forceinline__ ull pack2(float a, float b) {
    ull r; asm("mov.b64 %0, {%1, %2};" : "=l"(r) : "f"(a), "f"(b)); return r;
}
__device__ __forceinline__ void fma2(ull& d, ull a, ull b) {
    asm("fma.rn.f32x2 %0, %1, %2, %0;" : "+l"(d) : "l"(a), "l"(b));
}
union F2 { ull u; float2 f; };

// ---------------- kernel 1: P = emb @ W_ih^T (NT gemm), permuted cols, f32x2 ----------------
#define BM 128
#define BN 128
#define BK 32
__global__ void __launch_bounds__(256)
proj_kernel(const float* __restrict__ emb, const float* __restrict__ Wih) {
    __shared__ float As[BK][BM + 1];
    __shared__ float Bs[BK][BN + 1];
    int l  = threadIdx.x;
    int v0 = blockIdx.x * BM;
    int j0 = blockIdx.y * BN;
    int ty = l >> 4, tx = l & 15;

    ull acc2[8][4];
#pragma unroll
    for (int i = 0; i < 8; i++)
#pragma unroll
        for (int j = 0; j < 4; j++) acc2[i][j] = 0ull;

    for (int kt = 0; kt < EDIM; kt += BK) {
        for (int idx = l; idx < BM * BK; idx += 256) {
            int vr = idx >> 5; int e = idx & 31;
            int v = v0 + vr;
            As[e][vr] = (v < VOCAB) ? emb[v * EDIM + kt + e] : 0.f;
        }
        for (int idx = l; idx < BN * BK; idx += 256) {
            int jr = idx >> 5; int e = idx & 31;
            Bs[e][jr] = Wih[(j0 + jr) * EDIM + kt + e];
        }
        __syncthreads();
#pragma unroll
        for (int kk = 0; kk < BK; kk++) {
            float a[8], b[8];
#pragma unroll
            for (int i = 0; i < 8; i++) a[i] = As[kk][ty * 8 + i];
#pragma unroll
            for (int i = 0; i < 8; i++) b[i] = Bs[kk][tx * 8 + i];
            ull pa[8], pb[4];
#pragma unroll
            for (int i = 0; i < 8; i++) pa[i] = pack2(a[i], a[i]);
#pragma unroll
            for (int j = 0; j < 4; j++) pb[j] = pack2(b[2 * j], b[2 * j + 1]);
#pragma unroll
            for (int i = 0; i < 8; i++)
#pragma unroll
                for (int j = 0; j < 4; j++) fma2(acc2[i][j], pa[i], pb[j]);
        }
        __syncthreads();
    }
    int jb  = j0 + tx * 8;
    int pj0 = permj(jb);
#pragma unroll
    for (int i = 0; i < 8; i++) {
        int v = v0 + ty * 8 + i;
        if (v < VOCAB) {
#pragma unroll
            for (int j = 0; j < 4; j++) {
                F2 x; x.u = acc2[i][j];
                d_P[(size_t)v * G4 + pj0 + 2 * j]     = x.f.x;
                d_P[(size_t)v * G4 + pj0 + 2 * j + 1] = x.f.y;
            }
        }
    }
}

// ---------------- kernel 2: persistent cluster LSTM + fused compaction ----------------
__device__ __forceinline__ void cluster_sync_() {
    asm volatile("barrier.cluster.arrive.aligned;" ::: "memory");
    asm volatile("barrier.cluster.wait.aligned;" ::: "memory");
}
__device__ __forceinline__ float sigf(float x) {
    return __fdividef(1.f, 1.f + __expf(-x));
}
__device__ __forceinline__ float tanhfast(float x) {
    return 1.f - 2.f * __fdividef(1.f, __expf(2.f * x) + 1.f);
}
__device__ __forceinline__ void mbar_wait_parity(uint32_t addr, uint32_t ph) {
    uint32_t done;
    asm volatile("{\n\t.reg .pred p;\n\t"
                 "mbarrier.try_wait.parity.acquire.cta.shared::cta.b64 p, [%1], %2;\n\t"
                 "selp.b32 %0, 1, 0, p;\n\t}"
                 : "=r"(done) : "r"(addr), "r"(ph) : "memory");
    if (!done) {
        asm volatile("{\n\t.reg .pred P1;\n\t"
                     "WL_%=:\n\t"
                     "mbarrier.try_wait.parity.acquire.cta.shared::cta.b64 P1, [%0], %1, 0x989680;\n\t"
                     "@P1 bra.uni WD_%=;\n\t"
                     "bra.uni WL_%=;\n\t"
                     "WD_%=:\n\t}"
                     :: "r"(addr), "r"(ph) : "memory");
    }
}

// smem float layout
#define SM_MB    0        // 4 floats = 2 x u64 mbarriers (16B)
#define SM_HB    4        // 2048 : 2 par x 4 col x 256 k
#define SM_PART  2052     // 1024 : 2 kh x 128 row x 4 col (float4/row); int scratch reuse
#define SM_WZ    3076     // 256
#define SM_TOK   3332     // 8 ints (2 par x 4 col)
#define SM_ZB    3340     // 64 ints of z bits
#define SM_FLOATS 3408
#define LSTM_SMEM_BYTES (SM_FLOATS * 4)

__global__ void __launch_bounds__(256, 1) __cluster_dims__(8, 1, 1)
lstm_kernel(const int* __restrict__ sentences, const float* __restrict__ noise,
            const float* __restrict__ W_hh, const float* __restrict__ b_ih,
            const float* __restrict__ b_hh,
            const float* __restrict__ W_z, const float* __restrict__ b_z_p,
            float* __restrict__ out) {
    extern __shared__ float sm[];
    float* sm_hbuf  = sm + SM_HB;
    float* sm_part  = sm + SM_PART;
    float* sm_Wz    = sm + SM_WZ;
    int*   sm_tok   = (int*)(sm + SM_TOK);
    int*   sm_zbits = (int*)(sm + SM_ZB);

    int tid = threadIdx.x;
    uint32_t r;
    asm("mov.u32 %0, %%cluster_ctarank;" : "=r"(r));
    int cid   = blockIdx.x >> 3;
    int colg0 = cid * 4;
    int row = tid & 127;          // gate-row within CTA slice (g*32+uu)
    int kh  = tid >> 7;           // K-half
    int u   = tid & 31;
    int col = (tid >> 5) & 3;
    int wrp = tid >> 5;

    // register-resident weights, loaded with inverse permutation:
    // slice row (g*32+uu) of CTA r  <->  original row j = g*256 + r*32 + uu
    ull wp[64];
    {
        int g = row >> 5, uu = row & 31;
        int j = g * 256 + (int)r * 32 + uu;
        const float2* wsrc = (const float2*)(W_hh + j * 256 + kh * 128);
#pragma unroll
        for (int i = 0; i < 64; i++) {
            float2 w = wsrc[i];
            wp[i] = pack2(w.x, w.y);
        }
    }

    sm_Wz[tid] = W_z[tid & 255];
    for (int idx = tid; idx < 2048; idx += 256) sm_hbuf[idx] = 0.f;
    for (int idx = tid; idx < 64; idx += 256) sm_zbits[idx] = 0;
    if (tid < 4) sm_tok[tid] = sentences[colg0 + tid];

    // mbarriers: init + pre-arm both parities (4096 tx bytes = 8 peers x 512B)
    uint32_t mb_local = (uint32_t)__cvta_generic_to_shared(sm + SM_MB);
    if (tid == 0) {
        asm volatile("mbarrier.init.shared.b64 [%0], 1;" :: "r"(mb_local)     : "memory");
        asm volatile("mbarrier.init.shared.b64 [%0], 1;" :: "r"(mb_local + 8) : "memory");
        asm volatile("mbarrier.arrive.expect_tx.shared.b64 _, [%0], 4096;" :: "r"(mb_local)     : "memory");
        asm volatile("mbarrier.arrive.expect_tx.shared.b64 _, [%0], 4096;" :: "r"(mb_local + 8) : "memory");
    }

    // pointwise constants (tid<128 -> unit u, col)
    float b0 = 0.f, b1 = 0.f, b2 = 0.f, b3 = 0.f, creg = 0.f;
    if (tid < 128) {
        int jb0 = (int)r * 32 + u;
        b0 = b_ih[jb0]       + b_hh[jb0];
        b1 = b_ih[jb0 + 256] + b_hh[jb0 + 256];
        b2 = b_ih[jb0 + 512] + b_hh[jb0 + 512];
        b3 = b_ih[jb0 + 768] + b_hh[jb0 + 768];
    }
    float bz = b_z_p[0];
    __syncthreads();

    // peer addresses for hbuf and mbarriers
    uint32_t hb_local = (uint32_t)__cvta_generic_to_shared(sm_hbuf);
    uint32_t peer_hb[8], peer_mb[8];
#pragma unroll
    for (int p = 0; p < 8; p++) {
        asm("mapa.shared::cluster.u32 %0, %1, %2;" : "=r"(peer_hb[p]) : "r"(hb_local), "r"(p));
        asm("mapa.shared::cluster.u32 %0, %1, %2;" : "=r"(peer_mb[p]) : "r"(mb_local), "r"(p));
    }

    float nz = 0.f;
    uint32_t ph0 = 0, ph1 = 0;      // phase parity for mbar[0], mbar[1]
    uint32_t zchunk = 0;
    cluster_sync_();                 // all mbarriers initialized cluster-wide

    for (int t = 0; t < T_STEPS; t++) {
        int par  = t & 1;
        int wpar = par ^ 1;

        // ---- x-gate loads for this step (pointwise threads), overlap matmul ----
        float xg0 = 0.f, xg1 = 0.f, xg2 = 0.f, xg3 = 0.f;
        if (tid < 128) {
            int tok = sm_tok[par * 4 + col];
            const float* Pp = d_P + (size_t)tok * G4 + (int)r * 128 + u;
            xg0 = Pp[0]; xg1 = Pp[32]; xg2 = Pp[64]; xg3 = Pp[96];
        }

        // ---- next-step token prefetch (warp 7 tail) ----
        int nxt_tok = 0;
        if (tid >= 252) {
            int tn = (t + 1 < T_STEPS) ? t + 1 : T_STEPS - 1;
            nxt_tok = sentences[tn * BATCH + colg0 + (tid - 252)];
        }

        // ---- recurrent matmul: row x 4 cols over K-half, weights in registers ----
        ull aA0 = 0ull, aB0 = 0ull, aA1 = 0ull, aB1 = 0ull;
        ull aA2 = 0ull, aB2 = 0ull, aA3 = 0ull, aB3 = 0ull;
        {
            const ulonglong2* hp0 = (const ulonglong2*)(sm_hbuf + par * 1024 + 0 * 256 + kh * 128);
            const ulonglong2* hp1 = (const ulonglong2*)(sm_hbuf + par * 1024 + 1 * 256 + kh * 128);
            const ulonglong2* hp2 = (const ulonglong2*)(sm_hbuf + par * 1024 + 2 * 256 + kh * 128);
            const ulonglong2* hp3 = (const ulonglong2*)(sm_hbuf + par * 1024 + 3 * 256 + kh * 128);
#pragma unroll
            for (int i = 0; i < 32; i++) {
                ulonglong2 h0 = hp0[i];
                fma2(aA0, wp[2 * i], h0.x); fma2(aB0, wp[2 * i + 1], h0.y);
                ulonglong2 h1 = hp1[i];
                fma2(aA1, wp[2 * i], h1.x); fma2(aB1, wp[2 * i + 1], h1.y);
                ulonglong2 h2 = hp2[i];
                fma2(aA2, wp[2 * i], h2.x); fma2(aB2, wp[2 * i + 1], h2.y);
                ulonglong2 h3 = hp3[i];
                fma2(aA3, wp[2 * i], h3.x); fma2(aB3, wp[2 * i + 1], h3.y);
            }
        }
        {
            F2 xa, xb;
            float s0, s1, s2, s3;
            xa.u = aA0; xb.u = aB0; s0 = (xa.f.x + xa.f.y) + (xb.f.x + xb.f.y);
            xa.u = aA1; xb.u = aB1; s1 = (xa.f.x + xa.f.y) + (xb.f.x + xb.f.y);
            xa.u = aA2; xb.u = aB2; s2 = (xa.f.x + xa.f.y) + (xb.f.x + xb.f.y);
            xa.u = aA3; xb.u = aB3; s3 = (xa.f.x + xa.f.y) + (xb.f.x + xb.f.y);
            ((float4*)sm_part)[kh * 128 + row] = make_float4(s0, s1, s2, s3);
        }
        __syncthreads();

        if (tid < 128) {
            // ---- pointwise: compute h, ship 8 x scalar st.async (R6-proven path) ----
            const float* p0 = sm_part;
            const float* p1 = sm_part + 512;
            float gi = p0[(u)      * 4 + col] + p1[(u)      * 4 + col] + xg0 + b0;
            float gf = p0[(32 + u) * 4 + col] + p1[(32 + u) * 4 + col] + xg1 + b1;
            float gg = p0[(64 + u) * 4 + col] + p1[(64 + u) * 4 + col] + xg2 + b2;
            float go = p0[(96 + u) * 4 + col] + p1[(96 + u) * 4 + col] + xg3 + b3;
            creg = sigf(gf) * creg + sigf(gi) * tanhfast(gg);
            float h = sigf(go) * tanhfast(creg);
            uint32_t off  = (uint32_t)(((wpar * 1024) + col * 256 + (int)r * 32 + u) * 4);
            uint32_t moff = (uint32_t)(wpar * 8);
#pragma unroll
            for (int p8 = 0; p8 < 8; p8++)
                asm volatile("st.async.shared::cluster.mbarrier::complete_tx::bytes.f32 [%0], %1, [%2];"
                             :: "r"(peer_hb[p8] + off), "f"(h), "r"(peer_mb[p8] + moff) : "memory");
        } else if (wrp == 5 && (int)r < 4) {
            // ---- pz/z for output t-1, off the pre-matmul critical path ----
            // Delivery: this warp itself acquired the full hbuf[par] at the end of
            // step t-1 (monolithic barrier). Overwrite: peers' t+1 ships need our
            // t ships + a full peer matmul (~2000 cyc) vs ~300 cyc here.
            if (t > 0) {
                float acc = 0.f;
                const float* hrow = sm_hbuf + par * 1024 + (int)r * 256;
#pragma unroll
                for (int jj = 0; jj < 8; jj++)
                    acc += hrow[u + jj * 32] * sm_Wz[u + jj * 32];
#pragma unroll
                for (int off = 16; off; off >>= 1)
                    acc += __shfl_down_sync(0xffffffffu, acc, off);
                if (u == 0) {
                    float pz = sigf(acc + bz);
                    int oi = t - 1;
                    int o = oi * BATCH + colg0 + (int)r;
                    uint32_t zb = (nz < pz) ? 1u : 0u;
                    out[o]        = pz;
                    out[TBsz + o] = (float)zb;
                    zchunk |= zb << (oi & 31);
                    if ((oi & 31) == 31) { sm_zbits[oi >> 5] = (int)zchunk; zchunk = 0; }
                }
            }
            if (u == 0) nz = noise[t * BATCH + colg0 + (int)r];
        }

        // stage next tokens while stores fly
        if (tid >= 252) sm_tok[((t + 1) & 1) * 4 + (tid - 252)] = nxt_tok;

        // ---- wait for all 8 CTAs' h-slices (4096 tx bytes), then re-arm ----
        if (wpar == 0) { mbar_wait_parity(mb_local,     ph0); ph0 ^= 1; }
        else           { mbar_wait_parity(mb_local + 8, ph1); ph1 ^= 1; }
        if (tid == 0)
            asm volatile("mbarrier.arrive.expect_tx.shared.b64 _, [%0], 4096;"
                         :: "r"(mb_local + (uint32_t)(wpar * 8)) : "memory");
    }

    // final pz for t_out = 2047 (h_2047 is in parity 0; all threads acquired it)
    if ((int)r < 4 && wrp == 5) {
        float acc = 0.f;
        const float* hrow = sm_hbuf + (int)r * 256;
#pragma unroll
        for (int jj = 0; jj < 8; jj++)
            acc += hrow[u + jj * 32] * sm_Wz[u + jj * 32];
#pragma unroll
        for (int off = 16; off; off >>= 1)
            acc += __shfl_down_sync(0xffffffffu, acc, off);
        if (u == 0) {
            float pz = sigf(acc + bz);
            int o = 2047 * BATCH + colg0 + (int)r;
            uint32_t zb = (nz < pz) ? 1u : 0u;
            out[o]        = pz;
            out[TBsz + o] = (float)zb;
            zchunk |= zb << 31;
            sm_zbits[63] = (int)zchunk;
        }
    }
    cluster_sync_();   // no CTA exits while peers' async stores may still target it
    __syncthreads();

    // ---- fused per-column compaction (CTA r<4 handles column colg0+r) ----
    {
        int b = colg0 + (int)r;
        int lane = tid & 31, w = tid >> 5;
        int* wsum = (int*)sm_part;          // scratch
        int* s_total = wsum + 8;

        uint32_t byte = ((uint32_t)sm_zbits[tid >> 2] >> ((tid & 3) * 8)) & 0xFFu;
        int cnt = __popc(byte);
        int x = cnt;
#pragma unroll
        for (int off = 1; off < 32; off <<= 1) {
            int y = __shfl_up_sync(0xffffffffu, x, off);
            if (lane >= off) x += y;
        }
        if (lane == 31) wsum[w] = x;
        __syncthreads();
        if (tid == 0) {
            int s = 0;
            for (int k = 0; k < 8; k++) { int v = wsum[k]; wsum[k] = s; s += v; }
            *s_total = s;
        }
        __syncthreads();
        if ((int)r < 4) {
            int base = wsum[w] + (x - cnt);
            int t0 = tid * 8;
            int pos = base;
#pragma unroll
            for (int k = 0; k < 8; k++) {
                if ((byte >> k) & 1u) {
                    out[2 * TBsz + pos * BATCH + b] = (float)sentences[(t0 + k) * BATCH + b];
                    pos++;
                }
            }
            int total = *s_total;
            for (int p = total + tid; p < T_STEPS; p += 256)
                out[2 * TBsz + p * BATCH + b] = 0.0f;   // PAD_ID = 0
            if (tid == 0) out[3 * TBsz + b] = (float)total;
        }
    }
}

// ---------------- launch ----------------
extern "C" void kernel_launch(void* const* d_in, const int* in_sizes, int n_in,
                              void* d_out, int out_size) {
    const int*   sentences = (const int*)  d_in[0];
    const float* noise     = (const float*)d_in[1];
    const float* emb       = (const float*)d_in[2];
    const float* W_ih      = (const float*)d_in[3];
    const float* W_hh      = (const float*)d_in[4];
    const float* b_ih      = (const float*)d_in[5];
    const float* b_hh      = (const float*)d_in[6];
    const float* W_z       = (const float*)d_in[7];
    const float* b_z       = (const float*)d_in[8];
    float* out = (float*)d_out;

    cudaFuncSetAttribute(lstm_kernel, cudaFuncAttributeMaxDynamicSharedMemorySize,
                         LSTM_SMEM_BYTES);

    proj_kernel<<<dim3((VOCAB + BM - 1) / BM, G4 / BN), 256>>>(emb, W_ih);
    lstm_kernel<<<128, 256, LSTM_SMEM_BYTES>>>(sentences, noise, W_hh, b_ih, b_hh,
                                               W_z, b_z, out);
}